// round 16
// baseline (speedup 1.0000x reference)
#include <cuda_runtime.h>
#include <cuda_fp16.h>
#include <math.h>
#include <stdint.h>

// Problem constants
#define B_   8
#define N_   4096
#define D_   768
#define H_   12
#define M_   64
#define L_   4
#define HD_  64
#define BM_  (B_ * M_)      // 512
#define DH_  (4 * D_)       // 3072
#define ATTN_SCALE 0.125f

// ---------------------------------------------------------------------------
// Scratch (device globals)
// ---------------------------------------------------------------------------
__device__ float g_x[BM_ * D_];
__device__ float g_bias2[L_ * H_ * HD_];
__device__ float g_x1[BM_ * D_];
__device__ float g_px[4 * B_ * M_ * D_];

// fp16 operand buffers
__device__ __half g_parth[8 * BM_ * D_];     // fp16 split-K partials
__device__ __half g_lat_h[B_ * N_ * D_];
__device__ __half g_latT_h[B_ * N_ * D_];
__device__ __half g_P[B_ * H_ * M_ * N_];
__device__ __half g_Wq_h[L_ * D_ * D_];
__device__ __half g_kw_h[L_ * H_ * D_ * HD_];
__device__ __half g_owT_h[L_ * D_ * D_];
__device__ __half g_w1T_h[L_ * D_ * DH_];
__device__ __half g_w2T_h[L_ * DH_ * D_];
__device__ __half g_Wf_h[L_ * H_ * D_ * HD_];
__device__ __half g_ot_h[B_ * H_ * M_ * D_];
__device__ __half g_sel_h[M_ * D_];
__device__ __half g_qu_h[BM_ * D_];
__device__ __half g_q2_h[BM_ * D_];
__device__ __half g_qt_h[B_ * H_ * M_ * D_];
__device__ __half g_o2_h[BM_ * D_];
__device__ __half g_x1_h[BM_ * D_];
__device__ __half g_hid_h[BM_ * DH_];

// ---------------------------------------------------------------------------
// helpers
// ---------------------------------------------------------------------------
__device__ __forceinline__ void mma_f16(float c[4], const uint32_t a[4], const uint32_t b[2])
{
    asm volatile(
        "mma.sync.aligned.m16n8k16.row.col.f32.f16.f16.f32 "
        "{%0,%1,%2,%3}, {%4,%5,%6,%7}, {%8,%9}, {%0,%1,%2,%3};\n"
        : "+f"(c[0]), "+f"(c[1]), "+f"(c[2]), "+f"(c[3])
        : "r"(a[0]), "r"(a[1]), "r"(a[2]), "r"(a[3]), "r"(b[0]), "r"(b[1]));
}
__device__ __forceinline__ uint32_t smem_u32(const void* p)
{
    return (uint32_t)__cvta_generic_to_shared(p);
}
__device__ __forceinline__ void cpasync16(uint32_t dst, const void* src, int sz)
{
    asm volatile("cp.async.cg.shared.global [%0], [%1], 16, %2;\n"
                 :: "r"(dst), "l"(src), "r"(sz));
}
__device__ __forceinline__ void cp_commit() { asm volatile("cp.async.commit_group;\n"); }
__device__ __forceinline__ void cp_wait2()  { asm volatile("cp.async.wait_group 2;\n"); }

// ---------------------------------------------------------------------------
// hgemm: fp16 tensor GEMM, C(fp32 or fp16) = alpha * A @ B^T (+bias)(+gelu)
// A: [M][K] row-major fp16 (lda). B: [N][K] k-major fp16 (ldb).
// CTA 128x128x32, 128 threads = 4 warps of 64x64 (mt4 x nt8), m16n8k16.
// 4-stage cp.async; fragments via ldmatrix.m8n8.x4 (pad-40 rows: conflict-free).
// Requires K%32==0, N%128==0; M arbitrary (guarded). Works for KT>=1.
// ---------------------------------------------------------------------------
#define HG_STAGES 4
#define HG_SMEM (2 * HG_STAGES * 128 * 40 * 2)   // 81920 bytes

__global__ __launch_bounds__(128, 2)
void hgemm_kernel(const __half* __restrict__ A, const __half* __restrict__ Bm,
                  float* __restrict__ C, __half* __restrict__ Ch,
                  const float* __restrict__ bias,
                  int M, int N, int K, int lda, int ldb, int ldc,
                  long sAi, long sAj, long sBi, long sBj, long sCi, long sCj,
                  long sbj, int J, float alpha, int act)
{
    extern __shared__ __half sm[];
    __half* As = sm;                         // [4][128][40]
    __half* Bs = sm + HG_STAGES * 128 * 40;  // [4][128][40]

    int bz = blockIdx.z;
    int bi = bz / J, bj = bz - bi * J;
    A  += (size_t)bi * sAi + (size_t)bj * sAj;
    Bm += (size_t)bi * sBi + (size_t)bj * sBj;
    if (bias) bias += (size_t)bj * sbj;
    size_t coff = (size_t)bi * sCi + (size_t)bj * sCj;

    const int tid = threadIdx.x;
    const int lane = tid & 31;
    const int g = lane >> 2, t = lane & 3;
    const int warp = tid >> 5;
    const int wm = (warp & 1) * 64;
    const int wn = (warp >> 1) * 64;
    const int row0 = blockIdx.y * 128;
    const int col0 = blockIdx.x * 128;

    const uint32_t sA = smem_u32(As);
    const uint32_t sB = smem_u32(Bs);

    // ldmatrix lane mapping
    const int sel = lane >> 3, l7 = lane & 7;
    const int a_m = (sel & 1) * 8 + l7;
    const int a_k = (sel >> 1) * 8;
    const int b_n = (sel >> 1) * 8 + l7;
    const int b_k = (sel & 1) * 8;

    float acc[4][8][4];
#pragma unroll
    for (int i = 0; i < 4; i++)
#pragma unroll
        for (int j = 0; j < 8; j++)
#pragma unroll
            for (int v = 0; v < 4; v++) acc[i][j][v] = 0.f;

    auto issue = [&](int st, int k0) {
#pragma unroll
        for (int s = 0; s < 4; s++) {
            int idx = s * 128 + tid;
            int row = idx >> 2;
            int ch  = (idx & 3) * 8;
            {
                int r = row0 + row;
                bool ok = (r < M);
                const __half* ga = ok ? (A + (size_t)r * lda + k0 + ch) : A;
                uint32_t da = sA + (uint32_t)(((st * 128 + row) * 40 + ch) * 2);
                cpasync16(da, ga, ok ? 16 : 0);
            }
            {
                const __half* gb = Bm + (size_t)(col0 + row) * ldb + k0 + ch;
                uint32_t db = sB + (uint32_t)(((st * 128 + row) * 40 + ch) * 2);
                cpasync16(db, gb, 16);
            }
        }
    };

    auto compute = [&](int buf) {
        const uint32_t Ab = sA + (uint32_t)(buf * (128 * 40) * 2);
        const uint32_t Bb = sB + (uint32_t)(buf * (128 * 40) * 2);
#pragma unroll
        for (int ko = 0; ko < 32; ko += 16) {
            uint32_t af[4][4];
#pragma unroll
            for (int mt = 0; mt < 4; mt++) {
                uint32_t addr = Ab + (uint32_t)((((wm + mt * 16 + a_m) * 40) + ko + a_k) * 2);
                asm volatile(
                    "ldmatrix.sync.aligned.m8n8.x4.shared.b16 {%0,%1,%2,%3}, [%4];"
                    : "=r"(af[mt][0]), "=r"(af[mt][1]), "=r"(af[mt][2]), "=r"(af[mt][3])
                    : "r"(addr));
            }
            uint32_t bf[8][2];
#pragma unroll
            for (int p = 0; p < 4; p++) {
                uint32_t addr = Bb + (uint32_t)((((wn + p * 16 + b_n) * 40) + ko + b_k) * 2);
                asm volatile(
                    "ldmatrix.sync.aligned.m8n8.x4.shared.b16 {%0,%1,%2,%3}, [%4];"
                    : "=r"(bf[2 * p][0]), "=r"(bf[2 * p][1]),
                      "=r"(bf[2 * p + 1][0]), "=r"(bf[2 * p + 1][1])
                    : "r"(addr));
            }
#pragma unroll
            for (int mt = 0; mt < 4; mt++)
#pragma unroll
                for (int nt = 0; nt < 8; nt++)
                    mma_f16(acc[mt][nt], af[mt], bf[nt]);
        }
    };

    const int KT = K >> 5;
#pragma unroll
    for (int s = 0; s < HG_STAGES - 1; s++) {
        if (s < KT) issue(s, s * 32);
        cp_commit();
    }

    for (int kt = 0; kt < KT; kt++) {
        cp_wait2();
        __syncthreads();
        compute(kt & 3);
        int ns = kt + HG_STAGES - 1;
        if (ns < KT) issue(ns & 3, ns * 32);
        cp_commit();
    }

    // Epilogue
#pragma unroll
    for (int mt = 0; mt < 4; mt++) {
#pragma unroll
        for (int v = 0; v < 2; v++) {
            int r = row0 + wm + mt * 16 + g + v * 8;
            if (r >= M) continue;
#pragma unroll
            for (int nt = 0; nt < 8; nt++) {
                int c = col0 + wn + nt * 8 + 2 * t;
                float v0 = acc[mt][nt][v * 2 + 0] * alpha;
                float v1 = acc[mt][nt][v * 2 + 1] * alpha;
                if (bias) { v0 += bias[c]; v1 += bias[c + 1]; }
                if (act == 1) {
                    v0 = 0.5f * v0 * (1.f + erff(v0 * 0.7071067811865475f));
                    v1 = 0.5f * v1 * (1.f + erff(v1 * 0.7071067811865475f));
                }
                if (Ch) {
                    *(__half2*)&Ch[coff + (size_t)r * ldc + c] = __floats2half2_rn(v0, v1);
                } else {
                    *(float2*)&C[coff + (size_t)r * ldc + c] = make_float2(v0, v1);
                }
            }
        }
    }
}

// ---------------------------------------------------------------------------
// sgemm64: fp32 GEMM for small shapes, optional fp16 output. (pre-pass Wf)
// ---------------------------------------------------------------------------
template <bool TRANSB>
__global__ __launch_bounds__(128)
void sgemm64_kernel(const float* __restrict__ A, const float* __restrict__ Bm,
                    float* __restrict__ C, __half* __restrict__ Ch,
                    const float* __restrict__ bias,
                    int K, int lda, int ldb, int ldc,
                    long sAi, long sAj, long sBi, long sBj, long sCi, long sCj,
                    long sbj, int J, float alpha)
{
    __shared__ float As[2][16][68];
    __shared__ float Bs[2][16][68];

    int bz = blockIdx.z;
    int bi = bz / J, bj = bz - bi * J;
    A  += (size_t)bi * sAi + (size_t)bj * sAj;
    Bm += (size_t)bi * sBi + (size_t)bj * sBj;
    size_t coff = (size_t)bi * sCi + (size_t)bj * sCj;
    if (bias) bias += (size_t)bj * sbj;

    const int tid = threadIdx.x;
    const int row_t = tid & 15;
    const int col_t = tid >> 4;
    const int row0 = blockIdx.y * 64;
    const int col0 = blockIdx.x * 64;

    const int l_r  = tid >> 1;
    const int l_kc = (tid & 1) * 8;
    const int lb_k = tid >> 3;
    const int lb_n = (tid & 7) * 8;

    float acc[4][8];
#pragma unroll
    for (int i = 0; i < 4; i++)
#pragma unroll
        for (int j = 0; j < 8; j++) acc[i][j] = 0.f;

    auto load = [&](int buf, int k0) {
        {
            const float* p = A + (size_t)(row0 + l_r) * lda + k0 + l_kc;
            float4 v0 = *(const float4*)p;
            float4 v1 = *(const float4*)(p + 4);
            As[buf][l_kc + 0][l_r] = v0.x; As[buf][l_kc + 1][l_r] = v0.y;
            As[buf][l_kc + 2][l_r] = v0.z; As[buf][l_kc + 3][l_r] = v0.w;
            As[buf][l_kc + 4][l_r] = v1.x; As[buf][l_kc + 5][l_r] = v1.y;
            As[buf][l_kc + 6][l_r] = v1.z; As[buf][l_kc + 7][l_r] = v1.w;
        }
        if (TRANSB) {
            const float* p = Bm + (size_t)(col0 + l_r) * ldb + k0 + l_kc;
            float4 v0 = *(const float4*)p;
            float4 v1 = *(const float4*)(p + 4);
            Bs[buf][l_kc + 0][l_r] = v0.x; Bs[buf][l_kc + 1][l_r] = v0.y;
            Bs[buf][l_kc + 2][l_r] = v0.z; Bs[buf][l_kc + 3][l_r] = v0.w;
            Bs[buf][l_kc + 4][l_r] = v1.x; Bs[buf][l_kc + 5][l_r] = v1.y;
            Bs[buf][l_kc + 6][l_r] = v1.z; Bs[buf][l_kc + 7][l_r] = v1.w;
        } else {
            const float* p = Bm + (size_t)(k0 + lb_k) * ldb + col0 + lb_n;
            *(float4*)&Bs[buf][lb_k][lb_n] = *(const float4*)p;
            *(float4*)&Bs[buf][lb_k][lb_n + 4] = *(const float4*)(p + 4);
        }
    };

    load(0, 0);
    __syncthreads();
    int buf = 0;
    for (int k0 = 0; k0 < K; k0 += 16) {
        if (k0 + 16 < K) load(buf ^ 1, k0 + 16);
#pragma unroll
        for (int kk = 0; kk < 16; kk++) {
            float4 a = *(const float4*)&As[buf][kk][row_t * 4];
            float4 b0 = *(const float4*)&Bs[buf][kk][col_t * 8];
            float4 b1 = *(const float4*)&Bs[buf][kk][col_t * 8 + 4];
            float ar[4] = {a.x, a.y, a.z, a.w};
            float br[8] = {b0.x, b0.y, b0.z, b0.w, b1.x, b1.y, b1.z, b1.w};
#pragma unroll
            for (int i = 0; i < 4; i++)
#pragma unroll
                for (int j = 0; j < 8; j++) acc[i][j] += ar[i] * br[j];
        }
        buf ^= 1;
        __syncthreads();
    }

#pragma unroll
    for (int i = 0; i < 4; i++) {
        int r = row0 + row_t * 4 + i;
#pragma unroll
        for (int j = 0; j < 8; j++) {
            int c = col0 + col_t * 8 + j;
            float v = acc[i][j] * alpha;
            if (bias) v += bias[c];
            if (Ch) Ch[coff + (size_t)r * ldc + c] = __float2half_rn(v);
            else    C[coff + (size_t)r * ldc + c] = v;
        }
    }
}

// ---------------------------------------------------------------------------
// sgemm64h: fp16-input / fp32-compute GEMM (NN only), 64x64 tile, for o2.
// ---------------------------------------------------------------------------
__global__ __launch_bounds__(128)
void sgemm64h_kernel(const __half* __restrict__ A, const __half* __restrict__ Bm,
                     __half* __restrict__ Ch, const float* __restrict__ bias,
                     int K, int lda, int ldb, int ldc,
                     long sAi, long sAj, long sBi, long sBj, long sCi, long sCj,
                     long sbj, int J)
{
    __shared__ float As[2][16][68];
    __shared__ float Bs[2][16][68];

    int bz = blockIdx.z;
    int bi = bz / J, bj = bz - bi * J;
    A  += (size_t)bi * sAi + (size_t)bj * sAj;
    Bm += (size_t)bi * sBi + (size_t)bj * sBj;
    size_t coff = (size_t)bi * sCi + (size_t)bj * sCj;
    if (bias) bias += (size_t)bj * sbj;

    const int tid = threadIdx.x;
    const int row_t = tid & 15;
    const int col_t = tid >> 4;
    const int row0 = blockIdx.y * 64;
    const int col0 = blockIdx.x * 64;

    const int l_r  = tid >> 1;
    const int l_kc = (tid & 1) * 8;
    const int lb_k = tid >> 3;
    const int lb_n = (tid & 7) * 8;

    float acc[4][8];
#pragma unroll
    for (int i = 0; i < 4; i++)
#pragma unroll
        for (int j = 0; j < 8; j++) acc[i][j] = 0.f;

    auto load = [&](int buf, int k0) {
        {
            const __half* p = A + (size_t)(row0 + l_r) * lda + k0 + l_kc;
            uint4 u = *(const uint4*)p;
            float2 f0 = __half22float2(*(__half2*)&u.x);
            float2 f1 = __half22float2(*(__half2*)&u.y);
            float2 f2 = __half22float2(*(__half2*)&u.z);
            float2 f3 = __half22float2(*(__half2*)&u.w);
            As[buf][l_kc + 0][l_r] = f0.x; As[buf][l_kc + 1][l_r] = f0.y;
            As[buf][l_kc + 2][l_r] = f1.x; As[buf][l_kc + 3][l_r] = f1.y;
            As[buf][l_kc + 4][l_r] = f2.x; As[buf][l_kc + 5][l_r] = f2.y;
            As[buf][l_kc + 6][l_r] = f3.x; As[buf][l_kc + 7][l_r] = f3.y;
        }
        {
            const __half* p = Bm + (size_t)(k0 + lb_k) * ldb + col0 + lb_n;
            uint4 u = *(const uint4*)p;
            float2 f0 = __half22float2(*(__half2*)&u.x);
            float2 f1 = __half22float2(*(__half2*)&u.y);
            float2 f2 = __half22float2(*(__half2*)&u.z);
            float2 f3 = __half22float2(*(__half2*)&u.w);
            Bs[buf][lb_k][lb_n + 0] = f0.x; Bs[buf][lb_k][lb_n + 1] = f0.y;
            Bs[buf][lb_k][lb_n + 2] = f1.x; Bs[buf][lb_k][lb_n + 3] = f1.y;
            Bs[buf][lb_k][lb_n + 4] = f2.x; Bs[buf][lb_k][lb_n + 5] = f2.y;
            Bs[buf][lb_k][lb_n + 6] = f3.x; Bs[buf][lb_k][lb_n + 7] = f3.y;
        }
    };

    load(0, 0);
    __syncthreads();
    int buf = 0;
    for (int k0 = 0; k0 < K; k0 += 16) {
        if (k0 + 16 < K) load(buf ^ 1, k0 + 16);
#pragma unroll
        for (int kk = 0; kk < 16; kk++) {
            float4 a = *(const float4*)&As[buf][kk][row_t * 4];
            float4 b0 = *(const float4*)&Bs[buf][kk][col_t * 8];
            float4 b1 = *(const float4*)&Bs[buf][kk][col_t * 8 + 4];
            float ar[4] = {a.x, a.y, a.z, a.w};
            float br[8] = {b0.x, b0.y, b0.z, b0.w, b1.x, b1.y, b1.z, b1.w};
#pragma unroll
            for (int i = 0; i < 4; i++)
#pragma unroll
                for (int j = 0; j < 8; j++) acc[i][j] += ar[i] * br[j];
        }
        buf ^= 1;
        __syncthreads();
    }

#pragma unroll
    for (int i = 0; i < 4; i++) {
        int r = row0 + row_t * 4 + i;
#pragma unroll
        for (int j = 0; j < 8; j++) {
            int c = col0 + col_t * 8 + j;
            float v = acc[i][j];
            if (bias) v += bias[c];
            Ch[coff + (size_t)r * ldc + c] = __float2half_rn(v);
        }
    }
}

// ---------------------------------------------------------------------------
// split-K reduce, fp32 partials (pooling x)
// ---------------------------------------------------------------------------
__global__ void reduce_kernel(const float* __restrict__ part, const float* __restrict__ bias,
                              float* __restrict__ outF, __half* __restrict__ outH,
                              int total, int C, long cs, int nb, int act)
{
    int i = blockIdx.x * 256 + threadIdx.x;
    if (i >= total) return;
    float s = 0.f;
    for (int c = 0; c < C; c++) s += part[i + (size_t)c * cs];
    if (bias) s += bias[i % nb];
    if (act) s = 0.5f * s * (1.f + erff(s * 0.7071067811865475f));
    if (outH) outH[i] = __float2half_rn(s);
    if (outF) outF[i] = s;
}

// split-K reduce, fp16 partials (q2)
__global__ void reduceh_kernel(const __half* __restrict__ part, const float* __restrict__ bias,
                               __half* __restrict__ outH, int total, int C, long cs, int nb)
{
    int i = blockIdx.x * 256 + threadIdx.x;
    if (i >= total) return;
    float s = 0.f;
    for (int c = 0; c < C; c++) s += __half2float(part[i + (size_t)c * cs]);
    if (bias) s += bias[i % nb];
    outH[i] = __float2half_rn(s);
}

// ---------------------------------------------------------------------------
// fused latent prep
// ---------------------------------------------------------------------------
__global__ void latprep_kernel(const float* __restrict__ in,
                               __half* __restrict__ outN, __half* __restrict__ outT)
{
    __shared__ float tbuf[32][33];
    size_t zo = (size_t)blockIdx.z * N_ * D_;
    int r0 = blockIdx.y * 32, c0 = blockIdx.x * 32;
    int tx = threadIdx.x, ty = threadIdx.y;
#pragma unroll
    for (int i = 0; i < 4; i++) {
        int r = r0 + ty + i * 8;
        float v = in[zo + (size_t)r * D_ + c0 + tx];
        tbuf[ty + i * 8][tx] = v;
        outN[zo + (size_t)r * D_ + c0 + tx] = __float2half_rn(v);
    }
    __syncthreads();
#pragma unroll
    for (int i = 0; i < 4; i++)
        outT[zo + (size_t)(c0 + ty + i * 8) * N_ + r0 + tx] = __float2half_rn(tbuf[tx][ty + i * 8]);
}

__global__ void tconv_kernel(const float* __restrict__ in, __half* __restrict__ out,
                             int R, int C, long sIn, long sOut)
{
    __shared__ float tbuf[32][33];
    in  += (size_t)blockIdx.z * sIn;
    out += (size_t)blockIdx.z * sOut;
    int r0 = blockIdx.y * 32, c0 = blockIdx.x * 32;
    int tx = threadIdx.x, ty = threadIdx.y;
#pragma unroll
    for (int i = 0; i < 4; i++)
        tbuf[ty + i * 8][tx] = in[(size_t)(r0 + ty + i * 8) * C + c0 + tx];
    __syncthreads();
#pragma unroll
    for (int i = 0; i < 4; i++)
        out[(size_t)(c0 + ty + i * 8) * R + r0 + tx] = __float2half_rn(tbuf[tx][ty + i * 8]);
}

__global__ void cvt_kernel(const float* __restrict__ in, __half* __restrict__ out, int n)
{
    int i = (blockIdx.x * 256 + threadIdx.x) * 4;
    if (i >= n) return;
    float4 v = *(const float4*)(in + i);
    *(__half2*)(out + i)     = __floats2half2_rn(v.x, v.y);
    *(__half2*)(out + i + 2) = __floats2half2_rn(v.z, v.w);
}

// ---------------------------------------------------------------------------
// softmax over 4096 cols: in-place fp16
// ---------------------------------------------------------------------------
__global__ __launch_bounds__(256)
void softmax4096h_kernel(__half* __restrict__ X)
{
    __half* row = X + (size_t)blockIdx.x * 4096;
    int tid = threadIdx.x;
    uint4 u0 = *(uint4*)(row + tid * 16);
    uint4 u1 = *(uint4*)(row + tid * 16 + 8);
    float v[16];
    {
        uint32_t w[8] = {u0.x, u0.y, u0.z, u0.w, u1.x, u1.y, u1.z, u1.w};
#pragma unroll
        for (int j = 0; j < 8; j++) {
            float2 f = __half22float2(*(__half2*)&w[j]);
            v[2 * j] = f.x; v[2 * j + 1] = f.y;
        }
    }
    float m = -1e30f;
#pragma unroll
    for (int j = 0; j < 16; j++) m = fmaxf(m, v[j]);
    __shared__ float red[8];
#pragma unroll
    for (int s = 16; s > 0; s >>= 1) m = fmaxf(m, __shfl_xor_sync(0xffffffffu, m, s));
    if ((tid & 31) == 0) red[tid >> 5] = m;
    __syncthreads();
    m = red[0];
#pragma unroll
    for (int w = 1; w < 8; w++) m = fmaxf(m, red[w]);

    float sum = 0.f;
#pragma unroll
    for (int j = 0; j < 16; j++) { v[j] = __expf(v[j] - m); sum += v[j]; }
#pragma unroll
    for (int s = 16; s > 0; s >>= 1) sum += __shfl_xor_sync(0xffffffffu, sum, s);
    __syncthreads();
    if ((tid & 31) == 0) red[tid >> 5] = sum;
    __syncthreads();
    sum = 0.f;
#pragma unroll
    for (int w = 0; w < 8; w++) sum += red[w];
    float inv = 1.f / sum;
#pragma unroll
    for (int j = 0; j < 8; j++)
        *(__half2*)(row + tid * 16 + 2 * j) = __floats2half2_rn(v[2 * j] * inv, v[2 * j + 1] * inv);
}

// ---------------------------------------------------------------------------
// Fused split-K reduce (fp16 partials) + residual(+qc) + LayerNorm (+ queries):
//   val[c] = sum_k part[...] + bias[c] + other[r*768+c] (+ qcrow[(r&63)*768+c])
//   out = LN(val)*g + beta   (fp32 out + optional fp16 out)
//   if quH: quH = fp16(out + qcnext[(r&63)*768+c])
// ---------------------------------------------------------------------------
__global__ void add_ln_red_kernel(const __half* __restrict__ part, int C, long cs,
                                  const float* __restrict__ bias,
                                  const float* __restrict__ other,
                                  const float* __restrict__ qcrow,
                                  const float* __restrict__ g, const float* __restrict__ beta,
                                  float* __restrict__ out, __half* __restrict__ outH,
                                  const float* __restrict__ qcnext, __half* __restrict__ quH)
{
    int r = blockIdx.x;
    const float* o = other + (size_t)r * D_;
    const float* qc = qcrow ? (qcrow + (size_t)(r & (M_ - 1)) * D_) : nullptr;
    const float* qn = qcnext ? (qcnext + (size_t)(r & (M_ - 1)) * D_) : nullptr;
    __shared__ float red[256];
    int tid = threadIdx.x;
    float v[3];
    float s = 0.f;
#pragma unroll
    for (int i = 0; i < 3; i++) {
        int c = tid + i * 256;
        float acc = o[c] + bias[c];
        if (qc) acc += qc[c];
        size_t base = (size_t)r * D_ + c;
        for (int k = 0; k < C; k++) acc += __half2float(part[base + (size_t)k * cs]);
        v[i] = acc;
        s += acc;
    }
    red[tid] = s; __syncthreads();
    for (int st = 128; st > 0; st >>= 1) {
        if (tid < st) red[tid] += red[tid + st];
        __syncthreads();
    }
    float mean = red[0] * (1.f / D_);
    __syncthreads();
    s = 0.f;
#pragma unroll
    for (int i = 0; i < 3; i++) { float d = v[i] - mean; s += d * d; }
    red[tid] = s; __syncthreads();
    for (int st = 128; st > 0; st >>= 1) {
        if (tid < st) red[tid] += red[tid + st];
        __syncthreads();
    }
    float rstd = rsqrtf(red[0] * (1.f / D_) + 1e-5f);
#pragma unroll
    for (int i = 0; i < 3; i++) {
        int c = tid + i * 256;
        float oo = (v[i] - mean) * rstd * g[c] + beta[c];
        out[(size_t)r * D_ + c] = oo;
        if (outH) outH[(size_t)r * D_ + c] = __float2half_rn(oo);
        if (quH)  quH[(size_t)r * D_ + c] = __float2half_rn(oo + qn[c]);
    }
}

// queries (fp16 only) = x + qc   (layer 0 only)
__global__ void make_queries_kernel(const float* __restrict__ x, const float* __restrict__ qc,
                                    __half* __restrict__ qh)
{
    int i = blockIdx.x * 256 + threadIdx.x;
    int d = i % D_;
    int m = (i / D_) & (M_ - 1);
    qh[i] = __float2half_rn(x[i] + qc[m * D_ + d]);
}

// bias2[lh,f] = sum_e vb[lh,e]*hw[lh,e,f] + hb[lh,f]
__global__ void bias2_kernel(const float* __restrict__ vb, const float* __restrict__ hw,
                             const float* __restrict__ hb, float* __restrict__ out)
{
    int idx = blockIdx.x * 64 + threadIdx.x;
    int h = idx >> 6, f = idx & 63;
    const float* vbh = vb + h * 64;
    const float* hwh = hw + h * 4096;
    float s = hb[idx];
#pragma unroll 8
    for (int e = 0; e < 64; e++) s += vbh[e] * hwh[e * 64 + f];
    out[idx] = s;
}

// ---------------------------------------------------------------------------
// Host side
// ---------------------------------------------------------------------------
static void hgemm(const __half* A, const __half* B, float* C, __half* Ch, const float* bias,
                  int M, int N, int K, int lda, int ldb, int ldc,
                  long sAi, long sAj, long sBi, long sBj, long sCi, long sCj,
                  long sbj, int I, int J, float alpha, int act)
{
    dim3 grid(N / 128, (M + 127) / 128, I * J);
    hgemm_kernel<<<grid, 128, HG_SMEM>>>(A, B, C, Ch, bias, M, N, K, lda, ldb, ldc,
                                         sAi, sAj, sBi, sBj, sCi, sCj, sbj, J, alpha, act);
}

static void sgemm64(bool transB, const float* A, const float* B, float* C, __half* Ch,
                    const float* bias, int M, int N, int K, int lda, int ldb, int ldc,
                    long sAi, long sAj, long sBi, long sBj, long sCi, long sCj,
                    long sbj, int I, int J, float alpha)
{
    dim3 grid(N / 64, M / 64, I * J);
    if (transB)
        sgemm64_kernel<true><<<grid, 128>>>(A, B, C, Ch, bias, K, lda, ldb, ldc,
                                            sAi, sAj, sBi, sBj, sCi, sCj, sbj, J, alpha);
    else
        sgemm64_kernel<false><<<grid, 128>>>(A, B, C, Ch, bias, K, lda, ldb, ldc,
                                             sAi, sAj, sBi, sBj, sCi, sCj, sbj, J, alpha);
}

template <typename T>
static T* sym(const void* symbol)
{
    void* p = nullptr;
    cudaGetSymbolAddress(&p, symbol);
    return (T*)p;
}

extern "C" void kernel_launch(void* const* d_in, const int* in_sizes, int n_in,
                              void* d_out, int out_size)
{
    cudaFuncSetAttribute(hgemm_kernel, cudaFuncAttributeMaxDynamicSharedMemorySize, HG_SMEM);

    const float* latent = (const float*)d_in[0];
    const float* selector = (const float*)d_in[1];
    const float* qc = (const float*)d_in[2];
    const float* qw = (const float*)d_in[3];
    const float* qb = (const float*)d_in[4];
    const float* kw = (const float*)d_in[5];
    // kb (d_in[6]) cancels exactly in softmax
    const float* vw = (const float*)d_in[7];
    const float* vb = (const float*)d_in[8];
    const float* hw = (const float*)d_in[9];
    const float* hb = (const float*)d_in[10];
    const float* ow = (const float*)d_in[11];
    const float* ob = (const float*)d_in[12];
    const float* w1 = (const float*)d_in[13];
    const float* b1 = (const float*)d_in[14];
    const float* w2 = (const float*)d_in[15];
    const float* b2 = (const float*)d_in[16];
    const float* g1 = (const float*)d_in[17];
    const float* be1 = (const float*)d_in[18];
    const float* g2 = (const float*)d_in[19];
    const float* be2 = (const float*)d_in[20];

    float* x    = sym<float>(g_x);
    float* bi2  = sym<float>(g_bias2);
    float* x1   = sym<float>(g_x1);
    float* px   = sym<float>(g_px);
    __half* parth  = sym<__half>(g_parth);
    __half* lat_h  = sym<__half>(g_lat_h);
    __half* latT_h = sym<__half>(g_latT_h);
    __half* P      = sym<__half>(g_P);
    __half* Wq_h   = sym<__half>(g_Wq_h);
    __half* kw_h   = sym<__half>(g_kw_h);
    __half* owT_h  = sym<__half>(g_owT_h);
    __half* w1T_h  = sym<__half>(g_w1T_h);
    __half* w2T_h  = sym<__half>(g_w2T_h);
    __half* Wf_h   = sym<__half>(g_Wf_h);
    __half* ot_h   = sym<__half>(g_ot_h);
    __half* sel_h  = sym<__half>(g_sel_h);
    __half* qu_h   = sym<__half>(g_qu_h);
    __half* q2_h   = sym<__half>(g_q2_h);
    __half* qt_h   = sym<__half>(g_qt_h);
    __half* o2_h   = sym<__half>(g_o2_h);
    __half* x1_h   = sym<__half>(g_x1_h);
    __half* hid_h  = sym<__half>(g_hid_h);
    float* out = (float*)d_out;

    const long LAT_B = (long)N_ * D_;
    const long WHD   = (long)D_ * HD_;
    const long WL    = (long)H_ * WHD;
    const long PCH   = (long)BM_ * D_;
    const long HMD   = (long)H_ * M_ * D_;
    const long HMN   = (long)H_ * M_ * N_;

    dim3 tb(32, 8);

    // ---- pre-pass ----
    latprep_kernel<<<dim3(D_ / 32, N_ / 32, B_), tb>>>(latent, lat_h, latT_h);
    cvt_kernel<<<(M_ * D_) / 1024, 256>>>(selector, sel_h, M_ * D_);
    cvt_kernel<<<(L_ * H_ * D_ * HD_) / 1024, 256>>>(kw, kw_h, L_ * H_ * D_ * HD_);
    tconv_kernel<<<dim3(HD_ / 32, D_ / 32, L_ * H_), tb>>>(qw, Wq_h, D_, HD_, WHD, WHD);
    tconv_kernel<<<dim3(D_ / 32, D_ / 32, L_), tb>>>(ow, owT_h, D_, D_, (long)D_ * D_, (long)D_ * D_);
    tconv_kernel<<<dim3(DH_ / 32, D_ / 32, L_), tb>>>(w1, w1T_h, D_, DH_, (long)D_ * DH_, (long)D_ * DH_);
    tconv_kernel<<<dim3(D_ / 32, DH_ / 32, L_), tb>>>(w2, w2T_h, DH_, D_, (long)DH_ * D_, (long)DH_ * D_);
    sgemm64(false, vw, hw, nullptr, Wf_h, nullptr,
            D_, HD_, HD_, HD_, HD_, HD_,
            0, WHD, 0, (long)HD_ * HD_, 0, WHD, 0, 1, L_ * H_, 1.0f);
    bias2_kernel<<<L_ * H_, 64>>>(vb, hw, hb, bi2);

    // ---- pooling ----
    hgemm(sel_h, lat_h, nullptr, P, nullptr,
          M_, N_, D_, D_, D_, N_,
          0, 0, LAT_B, 0, (long)M_ * N_, 0, 0, B_, 1, 1.0f, 0);
    softmax4096h_kernel<<<B_ * M_, 256>>>(P);
    hgemm(P, latT_h, px, nullptr, nullptr,
          M_, D_, 1024, N_, N_, D_,
          (long)M_ * N_, 1024, LAT_B, 1024, (long)M_ * D_, (long)B_ * M_ * D_,
          0, B_, 4, 1.0f, 0);
    reduce_kernel<<<(B_ * M_ * D_ + 255) / 256, 256>>>(px, nullptr, x, nullptr,
                                                       B_ * M_ * D_, 4, (long)B_ * M_ * D_, D_, 0);
    // queries for layer 0
    make_queries_kernel<<<(BM_ * D_) / 256, 256>>>(x, qc, qu_h);

    for (int l = 0; l < L_; l++) {
        // q2 = queries @ Wq[l]^T + qb[l]  (fp16, split-K 8; fp16 partials)
        hgemm(qu_h, Wq_h + (long)l * D_ * D_, nullptr, parth, nullptr,
              BM_, D_, 96, D_, D_, D_,
              0, 96, 0, 96, 0, PCH, 0, 1, 8, 1.0f, 0);
        reduceh_kernel<<<(BM_ * D_ + 255) / 256, 256>>>(parth, qb + (long)l * D_, q2_h,
                                                        BM_ * D_, 8, PCH, D_);

        // qt_h = q2_h @ kw_h^T  (tensor fp16; batched (b,h), K=64)
        hgemm(q2_h, kw_h + (long)l * WL, nullptr, qt_h, nullptr,
              M_, D_, HD_, D_, HD_, D_,
              (long)M_ * D_, HD_, 0, WHD, HMD, (long)M_ * D_,
              0, B_, H_, 1.0f, 0);

        // S-logits written fp16 straight into P  (batched b)
        hgemm(qt_h, lat_h, nullptr, P, nullptr,
              H_ * M_, N_, D_, D_, D_, N_,
              HMD, 0, LAT_B, 0, HMN, 0,
              0, B_, 1, ATTN_SCALE, 0);

        softmax4096h_kernel<<<B_ * H_ * M_, 256>>>(P);

        // ot (fp16) = P @ latent  (batched b; B = latT_h)
        hgemm(P, latT_h, nullptr, ot_h, nullptr,
              H_ * M_, D_, N_, N_, N_, D_,
              HMN, 0, LAT_B, 0, HMD, 0,
              0, B_, 1, 1.0f, 0);

        // o2_h = ot_h @ Wf_h[l] + bias2[l]  (fp16 in, fp32 FFMA; batched (b,h))
        {
            dim3 grid(1, 1, B_ * H_);
            sgemm64h_kernel<<<grid, 128>>>(ot_h, Wf_h + (long)l * WL, o2_h,
                                           bi2 + (long)l * H_ * HD_,
                                           D_, D_, HD_, D_,
                                           HMD, WHD, 0, WHD, (long)M_ * D_, HD_,
                                           HD_, H_);
        }

        // o3 partials (fp16) = o2 @ ow[l]  (split-K 8)
        hgemm(o2_h, owT_h + (long)l * D_ * D_, nullptr, parth, nullptr,
              BM_, D_, 96, D_, D_, D_,
              0, 96, 0, 96, 0, PCH, 0, 1, 8, 1.0f, 0);
        // x1 = LN(sum(part) + ob + x + qc[l])
        add_ln_red_kernel<<<BM_, 256>>>(parth, 8, PCH, ob + (long)l * D_, x,
                                        qc + (long)l * M_ * D_,
                                        g1 + (long)l * D_, be1 + (long)l * D_, x1, x1_h,
                                        nullptr, nullptr);

        // hid = gelu(x1 @ w1 + b1)  (fp16, unsplit, bias+gelu in epilogue)
        hgemm(x1_h, w1T_h + (long)l * D_ * DH_, nullptr, hid_h, b1 + (long)l * DH_,
              BM_, DH_, D_, D_, D_, DH_,
              0, 0, 0, 0, 0, 0, 0, 1, 1, 1.0f, 1);

        // mout partials (fp16) = hid @ w2  (split-K 8)
        hgemm(hid_h, w2T_h + (long)l * DH_ * D_, nullptr, parth, nullptr,
              BM_, D_, 384, DH_, DH_, D_,
              0, 384, 0, 384, 0, PCH, 0, 1, 8, 1.0f, 0);
        // x = LN(sum(part) + b2 + x1); fuse next layer's queries when l < L-1
        if (l == L_ - 1) {
            add_ln_red_kernel<<<BM_, 256>>>(parth, 8, PCH, b2 + (long)l * D_, x1, nullptr,
                                            g2 + (long)l * D_, be2 + (long)l * D_,
                                            out, nullptr, nullptr, nullptr);
        } else {
            add_ln_red_kernel<<<BM_, 256>>>(parth, 8, PCH, b2 + (long)l * D_, x1, nullptr,
                                            g2 + (long)l * D_, be2 + (long)l * D_,
                                            x, nullptr,
                                            qc + (long)(l + 1) * M_ * D_, qu_h);
        }
    }
}

// round 17
// speedup vs baseline: 1.0088x; 1.0088x over previous
#include <cuda_runtime.h>
#include <cuda_fp16.h>
#include <math.h>
#include <stdint.h>

// Problem constants
#define B_   8
#define N_   4096
#define D_   768
#define H_   12
#define M_   64
#define L_   4
#define HD_  64
#define BM_  (B_ * M_)      // 512
#define DH_  (4 * D_)       // 3072
#define ATTN_SCALE 0.125f

// ---------------------------------------------------------------------------
// Scratch (device globals)
// ---------------------------------------------------------------------------
__device__ float g_x[BM_ * D_];
__device__ float g_bias2[L_ * H_ * HD_];
__device__ float g_x1[BM_ * D_];
__device__ float g_part[8 * BM_ * D_];
__device__ float g_px[4 * B_ * M_ * D_];

// fp16 operand buffers
__device__ __half g_lat_h[B_ * N_ * D_];
__device__ __half g_latT_h[B_ * N_ * D_];
__device__ __half g_P[B_ * H_ * M_ * N_];
__device__ __half g_Wq_h[L_ * D_ * D_];
__device__ __half g_kw_h[L_ * H_ * D_ * HD_];
__device__ __half g_owT_h[L_ * D_ * D_];
__device__ __half g_w1T_h[L_ * D_ * DH_];
__device__ __half g_w2T_h[L_ * DH_ * D_];
__device__ __half g_Wf_h[L_ * H_ * D_ * HD_];
__device__ __half g_ot_h[B_ * H_ * M_ * D_];
__device__ __half g_sel_h[M_ * D_];
__device__ __half g_qu_h[BM_ * D_];
__device__ __half g_q2_h[BM_ * D_];
__device__ __half g_qt_h[B_ * H_ * M_ * D_];
__device__ __half g_o2_h[BM_ * D_];
__device__ __half g_x1_h[BM_ * D_];
__device__ __half g_hid_h[BM_ * DH_];

// ---------------------------------------------------------------------------
// helpers
// ---------------------------------------------------------------------------
__device__ __forceinline__ void mma_f16(float c[4], const uint32_t a[4], const uint32_t b[2])
{
    asm volatile(
        "mma.sync.aligned.m16n8k16.row.col.f32.f16.f16.f32 "
        "{%0,%1,%2,%3}, {%4,%5,%6,%7}, {%8,%9}, {%0,%1,%2,%3};\n"
        : "+f"(c[0]), "+f"(c[1]), "+f"(c[2]), "+f"(c[3])
        : "r"(a[0]), "r"(a[1]), "r"(a[2]), "r"(a[3]), "r"(b[0]), "r"(b[1]));
}
__device__ __forceinline__ uint32_t smem_u32(const void* p)
{
    return (uint32_t)__cvta_generic_to_shared(p);
}
__device__ __forceinline__ void cpasync16(uint32_t dst, const void* src, int sz)
{
    asm volatile("cp.async.cg.shared.global [%0], [%1], 16, %2;\n"
                 :: "r"(dst), "l"(src), "r"(sz));
}
__device__ __forceinline__ void cp_commit() { asm volatile("cp.async.commit_group;\n"); }
__device__ __forceinline__ void cp_wait2()  { asm volatile("cp.async.wait_group 2;\n"); }

// ---------------------------------------------------------------------------
// hgemm: fp16 tensor GEMM, C(fp32 or fp16) = alpha * A @ B^T (+bias)(+gelu)
// A: [M][K] row-major fp16 (lda). B: [N][K] k-major fp16 (ldb).
// CTA 128x128x32, 128 threads = 4 warps of 64x64 (mt4 x nt8), m16n8k16.
// 4-stage cp.async; fragments via ldmatrix.m8n8.x4 (pad-40 rows: conflict-free).
// Requires K%32==0, N%128==0; M arbitrary (guarded). Works for KT>=1.
// ---------------------------------------------------------------------------
#define HG_STAGES 4
#define HG_SMEM (2 * HG_STAGES * 128 * 40 * 2)   // 81920 bytes

__global__ __launch_bounds__(128, 2)
void hgemm_kernel(const __half* __restrict__ A, const __half* __restrict__ Bm,
                  float* __restrict__ C, __half* __restrict__ Ch,
                  const float* __restrict__ bias,
                  int M, int N, int K, int lda, int ldb, int ldc,
                  long sAi, long sAj, long sBi, long sBj, long sCi, long sCj,
                  long sbj, int J, float alpha, int act)
{
    extern __shared__ __half sm[];
    __half* As = sm;                         // [4][128][40]
    __half* Bs = sm + HG_STAGES * 128 * 40;  // [4][128][40]

    int bz = blockIdx.z;
    int bi = bz / J, bj = bz - bi * J;
    A  += (size_t)bi * sAi + (size_t)bj * sAj;
    Bm += (size_t)bi * sBi + (size_t)bj * sBj;
    if (bias) bias += (size_t)bj * sbj;
    size_t coff = (size_t)bi * sCi + (size_t)bj * sCj;

    const int tid = threadIdx.x;
    const int lane = tid & 31;
    const int g = lane >> 2, t = lane & 3;
    const int warp = tid >> 5;
    const int wm = (warp & 1) * 64;
    const int wn = (warp >> 1) * 64;
    const int row0 = blockIdx.y * 128;
    const int col0 = blockIdx.x * 128;

    const uint32_t sA = smem_u32(As);
    const uint32_t sB = smem_u32(Bs);

    // ldmatrix lane mapping
    const int sel = lane >> 3, l7 = lane & 7;
    const int a_m = (sel & 1) * 8 + l7;
    const int a_k = (sel >> 1) * 8;
    const int b_n = (sel >> 1) * 8 + l7;
    const int b_k = (sel & 1) * 8;

    float acc[4][8][4];
#pragma unroll
    for (int i = 0; i < 4; i++)
#pragma unroll
        for (int j = 0; j < 8; j++)
#pragma unroll
            for (int v = 0; v < 4; v++) acc[i][j][v] = 0.f;

    auto issue = [&](int st, int k0) {
#pragma unroll
        for (int s = 0; s < 4; s++) {
            int idx = s * 128 + tid;
            int row = idx >> 2;
            int ch  = (idx & 3) * 8;
            {
                int r = row0 + row;
                bool ok = (r < M);
                const __half* ga = ok ? (A + (size_t)r * lda + k0 + ch) : A;
                uint32_t da = sA + (uint32_t)(((st * 128 + row) * 40 + ch) * 2);
                cpasync16(da, ga, ok ? 16 : 0);
            }
            {
                const __half* gb = Bm + (size_t)(col0 + row) * ldb + k0 + ch;
                uint32_t db = sB + (uint32_t)(((st * 128 + row) * 40 + ch) * 2);
                cpasync16(db, gb, 16);
            }
        }
    };

    auto compute = [&](int buf) {
        const uint32_t Ab = sA + (uint32_t)(buf * (128 * 40) * 2);
        const uint32_t Bb = sB + (uint32_t)(buf * (128 * 40) * 2);
#pragma unroll
        for (int ko = 0; ko < 32; ko += 16) {
            uint32_t af[4][4];
#pragma unroll
            for (int mt = 0; mt < 4; mt++) {
                uint32_t addr = Ab + (uint32_t)((((wm + mt * 16 + a_m) * 40) + ko + a_k) * 2);
                asm volatile(
                    "ldmatrix.sync.aligned.m8n8.x4.shared.b16 {%0,%1,%2,%3}, [%4];"
                    : "=r"(af[mt][0]), "=r"(af[mt][1]), "=r"(af[mt][2]), "=r"(af[mt][3])
                    : "r"(addr));
            }
            uint32_t bf[8][2];
#pragma unroll
            for (int p = 0; p < 4; p++) {
                uint32_t addr = Bb + (uint32_t)((((wn + p * 16 + b_n) * 40) + ko + b_k) * 2);
                asm volatile(
                    "ldmatrix.sync.aligned.m8n8.x4.shared.b16 {%0,%1,%2,%3}, [%4];"
                    : "=r"(bf[2 * p][0]), "=r"(bf[2 * p][1]),
                      "=r"(bf[2 * p + 1][0]), "=r"(bf[2 * p + 1][1])
                    : "r"(addr));
            }
#pragma unroll
            for (int mt = 0; mt < 4; mt++)
#pragma unroll
                for (int nt = 0; nt < 8; nt++)
                    mma_f16(acc[mt][nt], af[mt], bf[nt]);
        }
    };

    const int KT = K >> 5;
#pragma unroll
    for (int s = 0; s < HG_STAGES - 1; s++) {
        if (s < KT) issue(s, s * 32);
        cp_commit();
    }

    for (int kt = 0; kt < KT; kt++) {
        cp_wait2();
        __syncthreads();
        compute(kt & 3);
        int ns = kt + HG_STAGES - 1;
        if (ns < KT) issue(ns & 3, ns * 32);
        cp_commit();
    }

    // Epilogue
#pragma unroll
    for (int mt = 0; mt < 4; mt++) {
#pragma unroll
        for (int v = 0; v < 2; v++) {
            int r = row0 + wm + mt * 16 + g + v * 8;
            if (r >= M) continue;
#pragma unroll
            for (int nt = 0; nt < 8; nt++) {
                int c = col0 + wn + nt * 8 + 2 * t;
                float v0 = acc[mt][nt][v * 2 + 0] * alpha;
                float v1 = acc[mt][nt][v * 2 + 1] * alpha;
                if (bias) { v0 += bias[c]; v1 += bias[c + 1]; }
                if (act == 1) {
                    v0 = 0.5f * v0 * (1.f + erff(v0 * 0.7071067811865475f));
                    v1 = 0.5f * v1 * (1.f + erff(v1 * 0.7071067811865475f));
                }
                if (Ch) {
                    *(__half2*)&Ch[coff + (size_t)r * ldc + c] = __floats2half2_rn(v0, v1);
                } else {
                    *(float2*)&C[coff + (size_t)r * ldc + c] = make_float2(v0, v1);
                }
            }
        }
    }
}

// ---------------------------------------------------------------------------
// sgemm64: fp32 GEMM for small shapes, optional fp16 output. (pre-pass Wf)
// ---------------------------------------------------------------------------
template <bool TRANSB>
__global__ __launch_bounds__(128)
void sgemm64_kernel(const float* __restrict__ A, const float* __restrict__ Bm,
                    float* __restrict__ C, __half* __restrict__ Ch,
                    const float* __restrict__ bias,
                    int K, int lda, int ldb, int ldc,
                    long sAi, long sAj, long sBi, long sBj, long sCi, long sCj,
                    long sbj, int J, float alpha)
{
    __shared__ float As[2][16][68];
    __shared__ float Bs[2][16][68];

    int bz = blockIdx.z;
    int bi = bz / J, bj = bz - bi * J;
    A  += (size_t)bi * sAi + (size_t)bj * sAj;
    Bm += (size_t)bi * sBi + (size_t)bj * sBj;
    size_t coff = (size_t)bi * sCi + (size_t)bj * sCj;
    if (bias) bias += (size_t)bj * sbj;

    const int tid = threadIdx.x;
    const int row_t = tid & 15;
    const int col_t = tid >> 4;
    const int row0 = blockIdx.y * 64;
    const int col0 = blockIdx.x * 64;

    const int l_r  = tid >> 1;
    const int l_kc = (tid & 1) * 8;
    const int lb_k = tid >> 3;
    const int lb_n = (tid & 7) * 8;

    float acc[4][8];
#pragma unroll
    for (int i = 0; i < 4; i++)
#pragma unroll
        for (int j = 0; j < 8; j++) acc[i][j] = 0.f;

    auto load = [&](int buf, int k0) {
        {
            const float* p = A + (size_t)(row0 + l_r) * lda + k0 + l_kc;
            float4 v0 = *(const float4*)p;
            float4 v1 = *(const float4*)(p + 4);
            As[buf][l_kc + 0][l_r] = v0.x; As[buf][l_kc + 1][l_r] = v0.y;
            As[buf][l_kc + 2][l_r] = v0.z; As[buf][l_kc + 3][l_r] = v0.w;
            As[buf][l_kc + 4][l_r] = v1.x; As[buf][l_kc + 5][l_r] = v1.y;
            As[buf][l_kc + 6][l_r] = v1.z; As[buf][l_kc + 7][l_r] = v1.w;
        }
        if (TRANSB) {
            const float* p = Bm + (size_t)(col0 + l_r) * ldb + k0 + l_kc;
            float4 v0 = *(const float4*)p;
            float4 v1 = *(const float4*)(p + 4);
            Bs[buf][l_kc + 0][l_r] = v0.x; Bs[buf][l_kc + 1][l_r] = v0.y;
            Bs[buf][l_kc + 2][l_r] = v0.z; Bs[buf][l_kc + 3][l_r] = v0.w;
            Bs[buf][l_kc + 4][l_r] = v1.x; Bs[buf][l_kc + 5][l_r] = v1.y;
            Bs[buf][l_kc + 6][l_r] = v1.z; Bs[buf][l_kc + 7][l_r] = v1.w;
        } else {
            const float* p = Bm + (size_t)(k0 + lb_k) * ldb + col0 + lb_n;
            *(float4*)&Bs[buf][lb_k][lb_n] = *(const float4*)p;
            *(float4*)&Bs[buf][lb_k][lb_n + 4] = *(const float4*)(p + 4);
        }
    };

    load(0, 0);
    __syncthreads();
    int buf = 0;
    for (int k0 = 0; k0 < K; k0 += 16) {
        if (k0 + 16 < K) load(buf ^ 1, k0 + 16);
#pragma unroll
        for (int kk = 0; kk < 16; kk++) {
            float4 a = *(const float4*)&As[buf][kk][row_t * 4];
            float4 b0 = *(const float4*)&Bs[buf][kk][col_t * 8];
            float4 b1 = *(const float4*)&Bs[buf][kk][col_t * 8 + 4];
            float ar[4] = {a.x, a.y, a.z, a.w};
            float br[8] = {b0.x, b0.y, b0.z, b0.w, b1.x, b1.y, b1.z, b1.w};
#pragma unroll
            for (int i = 0; i < 4; i++)
#pragma unroll
                for (int j = 0; j < 8; j++) acc[i][j] += ar[i] * br[j];
        }
        buf ^= 1;
        __syncthreads();
    }

#pragma unroll
    for (int i = 0; i < 4; i++) {
        int r = row0 + row_t * 4 + i;
#pragma unroll
        for (int j = 0; j < 8; j++) {
            int c = col0 + col_t * 8 + j;
            float v = acc[i][j] * alpha;
            if (bias) v += bias[c];
            if (Ch) Ch[coff + (size_t)r * ldc + c] = __float2half_rn(v);
            else    C[coff + (size_t)r * ldc + c] = v;
        }
    }
}

// ---------------------------------------------------------------------------
// sgemm64h: fp16-input / fp32-compute GEMM (NN only), 64x64 tile, for o2.
// ---------------------------------------------------------------------------
__global__ __launch_bounds__(128)
void sgemm64h_kernel(const __half* __restrict__ A, const __half* __restrict__ Bm,
                     __half* __restrict__ Ch, const float* __restrict__ bias,
                     int K, int lda, int ldb, int ldc,
                     long sAi, long sAj, long sBi, long sBj, long sCi, long sCj,
                     long sbj, int J)
{
    __shared__ float As[2][16][68];
    __shared__ float Bs[2][16][68];

    int bz = blockIdx.z;
    int bi = bz / J, bj = bz - bi * J;
    A  += (size_t)bi * sAi + (size_t)bj * sAj;
    Bm += (size_t)bi * sBi + (size_t)bj * sBj;
    size_t coff = (size_t)bi * sCi + (size_t)bj * sCj;
    if (bias) bias += (size_t)bj * sbj;

    const int tid = threadIdx.x;
    const int row_t = tid & 15;
    const int col_t = tid >> 4;
    const int row0 = blockIdx.y * 64;
    const int col0 = blockIdx.x * 64;

    const int l_r  = tid >> 1;
    const int l_kc = (tid & 1) * 8;
    const int lb_k = tid >> 3;
    const int lb_n = (tid & 7) * 8;

    float acc[4][8];
#pragma unroll
    for (int i = 0; i < 4; i++)
#pragma unroll
        for (int j = 0; j < 8; j++) acc[i][j] = 0.f;

    auto load = [&](int buf, int k0) {
        {
            const __half* p = A + (size_t)(row0 + l_r) * lda + k0 + l_kc;
            uint4 u = *(const uint4*)p;
            float2 f0 = __half22float2(*(__half2*)&u.x);
            float2 f1 = __half22float2(*(__half2*)&u.y);
            float2 f2 = __half22float2(*(__half2*)&u.z);
            float2 f3 = __half22float2(*(__half2*)&u.w);
            As[buf][l_kc + 0][l_r] = f0.x; As[buf][l_kc + 1][l_r] = f0.y;
            As[buf][l_kc + 2][l_r] = f1.x; As[buf][l_kc + 3][l_r] = f1.y;
            As[buf][l_kc + 4][l_r] = f2.x; As[buf][l_kc + 5][l_r] = f2.y;
            As[buf][l_kc + 6][l_r] = f3.x; As[buf][l_kc + 7][l_r] = f3.y;
        }
        {
            const __half* p = Bm + (size_t)(k0 + lb_k) * ldb + col0 + lb_n;
            uint4 u = *(const uint4*)p;
            float2 f0 = __half22float2(*(__half2*)&u.x);
            float2 f1 = __half22float2(*(__half2*)&u.y);
            float2 f2 = __half22float2(*(__half2*)&u.z);
            float2 f3 = __half22float2(*(__half2*)&u.w);
            Bs[buf][lb_k][lb_n + 0] = f0.x; Bs[buf][lb_k][lb_n + 1] = f0.y;
            Bs[buf][lb_k][lb_n + 2] = f1.x; Bs[buf][lb_k][lb_n + 3] = f1.y;
            Bs[buf][lb_k][lb_n + 4] = f2.x; Bs[buf][lb_k][lb_n + 5] = f2.y;
            Bs[buf][lb_k][lb_n + 6] = f3.x; Bs[buf][lb_k][lb_n + 7] = f3.y;
        }
    };

    load(0, 0);
    __syncthreads();
    int buf = 0;
    for (int k0 = 0; k0 < K; k0 += 16) {
        if (k0 + 16 < K) load(buf ^ 1, k0 + 16);
#pragma unroll
        for (int kk = 0; kk < 16; kk++) {
            float4 a = *(const float4*)&As[buf][kk][row_t * 4];
            float4 b0 = *(const float4*)&Bs[buf][kk][col_t * 8];
            float4 b1 = *(const float4*)&Bs[buf][kk][col_t * 8 + 4];
            float ar[4] = {a.x, a.y, a.z, a.w};
            float br[8] = {b0.x, b0.y, b0.z, b0.w, b1.x, b1.y, b1.z, b1.w};
#pragma unroll
            for (int i = 0; i < 4; i++)
#pragma unroll
                for (int j = 0; j < 8; j++) acc[i][j] += ar[i] * br[j];
        }
        buf ^= 1;
        __syncthreads();
    }

#pragma unroll
    for (int i = 0; i < 4; i++) {
        int r = row0 + row_t * 4 + i;
#pragma unroll
        for (int j = 0; j < 8; j++) {
            int c = col0 + col_t * 8 + j;
            float v = acc[i][j];
            if (bias) v += bias[c];
            Ch[coff + (size_t)r * ldc + c] = __float2half_rn(v);
        }
    }
}

// ---------------------------------------------------------------------------
// split-K reduce (pooling x, q2)
// ---------------------------------------------------------------------------
__global__ void reduce_kernel(const float* __restrict__ part, const float* __restrict__ bias,
                              float* __restrict__ outF, __half* __restrict__ outH,
                              int total, int C, long cs, int nb, int act)
{
    int i = blockIdx.x * 256 + threadIdx.x;
    if (i >= total) return;
    float s = 0.f;
    for (int c = 0; c < C; c++) s += part[i + (size_t)c * cs];
    if (bias) s += bias[i % nb];
    if (act) s = 0.5f * s * (1.f + erff(s * 0.7071067811865475f));
    if (outH) outH[i] = __float2half_rn(s);
    if (outF) outF[i] = s;
}

// ---------------------------------------------------------------------------
// fused latent prep
// ---------------------------------------------------------------------------
__global__ void latprep_kernel(const float* __restrict__ in,
                               __half* __restrict__ outN, __half* __restrict__ outT)
{
    __shared__ float tbuf[32][33];
    size_t zo = (size_t)blockIdx.z * N_ * D_;
    int r0 = blockIdx.y * 32, c0 = blockIdx.x * 32;
    int tx = threadIdx.x, ty = threadIdx.y;
#pragma unroll
    for (int i = 0; i < 4; i++) {
        int r = r0 + ty + i * 8;
        float v = in[zo + (size_t)r * D_ + c0 + tx];
        tbuf[ty + i * 8][tx] = v;
        outN[zo + (size_t)r * D_ + c0 + tx] = __float2half_rn(v);
    }
    __syncthreads();
#pragma unroll
    for (int i = 0; i < 4; i++)
        outT[zo + (size_t)(c0 + ty + i * 8) * N_ + r0 + tx] = __float2half_rn(tbuf[tx][ty + i * 8]);
}

__global__ void tconv_kernel(const float* __restrict__ in, __half* __restrict__ out,
                             int R, int C, long sIn, long sOut)
{
    __shared__ float tbuf[32][33];
    in  += (size_t)blockIdx.z * sIn;
    out += (size_t)blockIdx.z * sOut;
    int r0 = blockIdx.y * 32, c0 = blockIdx.x * 32;
    int tx = threadIdx.x, ty = threadIdx.y;
#pragma unroll
    for (int i = 0; i < 4; i++)
        tbuf[ty + i * 8][tx] = in[(size_t)(r0 + ty + i * 8) * C + c0 + tx];
    __syncthreads();
#pragma unroll
    for (int i = 0; i < 4; i++)
        out[(size_t)(c0 + ty + i * 8) * R + r0 + tx] = __float2half_rn(tbuf[tx][ty + i * 8]);
}

__global__ void cvt_kernel(const float* __restrict__ in, __half* __restrict__ out, int n)
{
    int i = (blockIdx.x * 256 + threadIdx.x) * 4;
    if (i >= n) return;
    float4 v = *(const float4*)(in + i);
    *(__half2*)(out + i)     = __floats2half2_rn(v.x, v.y);
    *(__half2*)(out + i + 2) = __floats2half2_rn(v.z, v.w);
}

// ---------------------------------------------------------------------------
// softmax over 4096 cols: in-place fp16
// ---------------------------------------------------------------------------
__global__ __launch_bounds__(256)
void softmax4096h_kernel(__half* __restrict__ X)
{
    __half* row = X + (size_t)blockIdx.x * 4096;
    int tid = threadIdx.x;
    uint4 u0 = *(uint4*)(row + tid * 16);
    uint4 u1 = *(uint4*)(row + tid * 16 + 8);
    float v[16];
    {
        uint32_t w[8] = {u0.x, u0.y, u0.z, u0.w, u1.x, u1.y, u1.z, u1.w};
#pragma unroll
        for (int j = 0; j < 8; j++) {
            float2 f = __half22float2(*(__half2*)&w[j]);
            v[2 * j] = f.x; v[2 * j + 1] = f.y;
        }
    }
    float m = -1e30f;
#pragma unroll
    for (int j = 0; j < 16; j++) m = fmaxf(m, v[j]);
    __shared__ float red[8];
#pragma unroll
    for (int s = 16; s > 0; s >>= 1) m = fmaxf(m, __shfl_xor_sync(0xffffffffu, m, s));
    if ((tid & 31) == 0) red[tid >> 5] = m;
    __syncthreads();
    m = red[0];
#pragma unroll
    for (int w = 1; w < 8; w++) m = fmaxf(m, red[w]);

    float sum = 0.f;
#pragma unroll
    for (int j = 0; j < 16; j++) { v[j] = __expf(v[j] - m); sum += v[j]; }
#pragma unroll
    for (int s = 16; s > 0; s >>= 1) sum += __shfl_xor_sync(0xffffffffu, sum, s);
    __syncthreads();
    if ((tid & 31) == 0) red[tid >> 5] = sum;
    __syncthreads();
    sum = 0.f;
#pragma unroll
    for (int w = 0; w < 8; w++) sum += red[w];
    float inv = 1.f / sum;
#pragma unroll
    for (int j = 0; j < 8; j++)
        *(__half2*)(row + tid * 16 + 2 * j) = __floats2half2_rn(v[2 * j] * inv, v[2 * j + 1] * inv);
}

// ---------------------------------------------------------------------------
// Fused split-K reduce + residual(+qc) + LayerNorm (+ next-layer queries):
//   val[c] = sum_k part[...] + bias[c] + other[r*768+c] (+ qcrow[(r&63)*768+c])
//   out = LN(val)*g + beta   (fp32 out + optional fp16 out)
//   if quH: quH = fp16(out + qcnext[(r&63)*768+c])   (next layer's queries)
// ---------------------------------------------------------------------------
__global__ void add_ln_red_kernel(const float* __restrict__ part, int C, long cs,
                                  const float* __restrict__ bias,
                                  const float* __restrict__ other,
                                  const float* __restrict__ qcrow,
                                  const float* __restrict__ g, const float* __restrict__ beta,
                                  float* __restrict__ out, __half* __restrict__ outH,
                                  const float* __restrict__ qcnext, __half* __restrict__ quH)
{
    int r = blockIdx.x;
    const float* o = other + (size_t)r * D_;
    const float* qc = qcrow ? (qcrow + (size_t)(r & (M_ - 1)) * D_) : nullptr;
    const float* qn = qcnext ? (qcnext + (size_t)(r & (M_ - 1)) * D_) : nullptr;
    __shared__ float red[256];
    int tid = threadIdx.x;
    float v[3];
    float s = 0.f;
#pragma unroll
    for (int i = 0; i < 3; i++) {
        int c = tid + i * 256;
        float acc = o[c] + bias[c];
        if (qc) acc += qc[c];
        size_t base = (size_t)r * D_ + c;
        for (int k = 0; k < C; k++) acc += part[base + (size_t)k * cs];
        v[i] = acc;
        s += acc;
    }
    red[tid] = s; __syncthreads();
    for (int st = 128; st > 0; st >>= 1) {
        if (tid < st) red[tid] += red[tid + st];
        __syncthreads();
    }
    float mean = red[0] * (1.f / D_);
    __syncthreads();
    s = 0.f;
#pragma unroll
    for (int i = 0; i < 3; i++) { float d = v[i] - mean; s += d * d; }
    red[tid] = s; __syncthreads();
    for (int st = 128; st > 0; st >>= 1) {
        if (tid < st) red[tid] += red[tid + st];
        __syncthreads();
    }
    float rstd = rsqrtf(red[0] * (1.f / D_) + 1e-5f);
#pragma unroll
    for (int i = 0; i < 3; i++) {
        int c = tid + i * 256;
        float oo = (v[i] - mean) * rstd * g[c] + beta[c];
        out[(size_t)r * D_ + c] = oo;
        if (outH) outH[(size_t)r * D_ + c] = __float2half_rn(oo);
        if (quH)  quH[(size_t)r * D_ + c] = __float2half_rn(oo + qn[c]);
    }
}

// queries (fp16 only) = x + qc   (layer 0 only)
__global__ void make_queries_kernel(const float* __restrict__ x, const float* __restrict__ qc,
                                    __half* __restrict__ qh)
{
    int i = blockIdx.x * 256 + threadIdx.x;
    int d = i % D_;
    int m = (i / D_) & (M_ - 1);
    qh[i] = __float2half_rn(x[i] + qc[m * D_ + d]);
}

// bias2[lh,f] = sum_e vb[lh,e]*hw[lh,e,f] + hb[lh,f]
__global__ void bias2_kernel(const float* __restrict__ vb, const float* __restrict__ hw,
                             const float* __restrict__ hb, float* __restrict__ out)
{
    int idx = blockIdx.x * 64 + threadIdx.x;
    int h = idx >> 6, f = idx & 63;
    const float* vbh = vb + h * 64;
    const float* hwh = hw + h * 4096;
    float s = hb[idx];
#pragma unroll 8
    for (int e = 0; e < 64; e++) s += vbh[e] * hwh[e * 64 + f];
    out[idx] = s;
}

// ---------------------------------------------------------------------------
// Host side
// ---------------------------------------------------------------------------
static void hgemm(const __half* A, const __half* B, float* C, __half* Ch, const float* bias,
                  int M, int N, int K, int lda, int ldb, int ldc,
                  long sAi, long sAj, long sBi, long sBj, long sCi, long sCj,
                  long sbj, int I, int J, float alpha, int act)
{
    dim3 grid(N / 128, (M + 127) / 128, I * J);
    hgemm_kernel<<<grid, 128, HG_SMEM>>>(A, B, C, Ch, bias, M, N, K, lda, ldb, ldc,
                                         sAi, sAj, sBi, sBj, sCi, sCj, sbj, J, alpha, act);
}

static void sgemm64(bool transB, const float* A, const float* B, float* C, __half* Ch,
                    const float* bias, int M, int N, int K, int lda, int ldb, int ldc,
                    long sAi, long sAj, long sBi, long sBj, long sCi, long sCj,
                    long sbj, int I, int J, float alpha)
{
    dim3 grid(N / 64, M / 64, I * J);
    if (transB)
        sgemm64_kernel<true><<<grid, 128>>>(A, B, C, Ch, bias, K, lda, ldb, ldc,
                                            sAi, sAj, sBi, sBj, sCi, sCj, sbj, J, alpha);
    else
        sgemm64_kernel<false><<<grid, 128>>>(A, B, C, Ch, bias, K, lda, ldb, ldc,
                                             sAi, sAj, sBi, sBj, sCi, sCj, sbj, J, alpha);
}

template <typename T>
static T* sym(const void* symbol)
{
    void* p = nullptr;
    cudaGetSymbolAddress(&p, symbol);
    return (T*)p;
}

extern "C" void kernel_launch(void* const* d_in, const int* in_sizes, int n_in,
                              void* d_out, int out_size)
{
    cudaFuncSetAttribute(hgemm_kernel, cudaFuncAttributeMaxDynamicSharedMemorySize, HG_SMEM);

    const float* latent = (const float*)d_in[0];
    const float* selector = (const float*)d_in[1];
    const float* qc = (const float*)d_in[2];
    const float* qw = (const float*)d_in[3];
    const float* qb = (const float*)d_in[4];
    const float* kw = (const float*)d_in[5];
    // kb (d_in[6]) cancels exactly in softmax
    const float* vw = (const float*)d_in[7];
    const float* vb = (const float*)d_in[8];
    const float* hw = (const float*)d_in[9];
    const float* hb = (const float*)d_in[10];
    const float* ow = (const float*)d_in[11];
    const float* ob = (const float*)d_in[12];
    const float* w1 = (const float*)d_in[13];
    const float* b1 = (const float*)d_in[14];
    const float* w2 = (const float*)d_in[15];
    const float* b2 = (const float*)d_in[16];
    const float* g1 = (const float*)d_in[17];
    const float* be1 = (const float*)d_in[18];
    const float* g2 = (const float*)d_in[19];
    const float* be2 = (const float*)d_in[20];

    float* x    = sym<float>(g_x);
    float* bi2  = sym<float>(g_bias2);
    float* x1   = sym<float>(g_x1);
    float* part = sym<float>(g_part);
    float* px   = sym<float>(g_px);
    __half* lat_h  = sym<__half>(g_lat_h);
    __half* latT_h = sym<__half>(g_latT_h);
    __half* P      = sym<__half>(g_P);
    __half* Wq_h   = sym<__half>(g_Wq_h);
    __half* kw_h   = sym<__half>(g_kw_h);
    __half* owT_h  = sym<__half>(g_owT_h);
    __half* w1T_h  = sym<__half>(g_w1T_h);
    __half* w2T_h  = sym<__half>(g_w2T_h);
    __half* Wf_h   = sym<__half>(g_Wf_h);
    __half* ot_h   = sym<__half>(g_ot_h);
    __half* sel_h  = sym<__half>(g_sel_h);
    __half* qu_h   = sym<__half>(g_qu_h);
    __half* q2_h   = sym<__half>(g_q2_h);
    __half* qt_h   = sym<__half>(g_qt_h);
    __half* o2_h   = sym<__half>(g_o2_h);
    __half* x1_h   = sym<__half>(g_x1_h);
    __half* hid_h  = sym<__half>(g_hid_h);
    float* out = (float*)d_out;

    const long LAT_B = (long)N_ * D_;
    const long WHD   = (long)D_ * HD_;
    const long WL    = (long)H_ * WHD;
    const long PCH   = (long)BM_ * D_;
    const long HMD   = (long)H_ * M_ * D_;
    const long HMN   = (long)H_ * M_ * N_;

    dim3 tb(32, 8);

    // ---- pre-pass ----
    latprep_kernel<<<dim3(D_ / 32, N_ / 32, B_), tb>>>(latent, lat_h, latT_h);
    cvt_kernel<<<(M_ * D_) / 1024, 256>>>(selector, sel_h, M_ * D_);
    cvt_kernel<<<(L_ * H_ * D_ * HD_) / 1024, 256>>>(kw, kw_h, L_ * H_ * D_ * HD_);
    tconv_kernel<<<dim3(HD_ / 32, D_ / 32, L_ * H_), tb>>>(qw, Wq_h, D_, HD_, WHD, WHD);
    tconv_kernel<<<dim3(D_ / 32, D_ / 32, L_), tb>>>(ow, owT_h, D_, D_, (long)D_ * D_, (long)D_ * D_);
    tconv_kernel<<<dim3(DH_ / 32, D_ / 32, L_), tb>>>(w1, w1T_h, D_, DH_, (long)D_ * DH_, (long)D_ * DH_);
    tconv_kernel<<<dim3(D_ / 32, DH_ / 32, L_), tb>>>(w2, w2T_h, DH_, D_, (long)DH_ * D_, (long)DH_ * D_);
    sgemm64(false, vw, hw, nullptr, Wf_h, nullptr,
            D_, HD_, HD_, HD_, HD_, HD_,
            0, WHD, 0, (long)HD_ * HD_, 0, WHD, 0, 1, L_ * H_, 1.0f);
    bias2_kernel<<<L_ * H_, 64>>>(vb, hw, hb, bi2);

    // ---- pooling ----
    hgemm(sel_h, lat_h, nullptr, P, nullptr,
          M_, N_, D_, D_, D_, N_,
          0, 0, LAT_B, 0, (long)M_ * N_, 0, 0, B_, 1, 1.0f, 0);
    softmax4096h_kernel<<<B_ * M_, 256>>>(P);
    hgemm(P, latT_h, px, nullptr, nullptr,
          M_, D_, 1024, N_, N_, D_,
          (long)M_ * N_, 1024, LAT_B, 1024, (long)M_ * D_, (long)B_ * M_ * D_,
          0, B_, 4, 1.0f, 0);
    reduce_kernel<<<(B_ * M_ * D_ + 255) / 256, 256>>>(px, nullptr, x, nullptr,
                                                       B_ * M_ * D_, 4, (long)B_ * M_ * D_, D_, 0);
    // queries for layer 0
    make_queries_kernel<<<(BM_ * D_) / 256, 256>>>(x, qc, qu_h);

    for (int l = 0; l < L_; l++) {
        // q2 = queries @ Wq[l]^T + qb[l]  (fp16, split-K 8; fp16 result)
        hgemm(qu_h, Wq_h + (long)l * D_ * D_, part, nullptr, nullptr,
              BM_, D_, 96, D_, D_, D_,
              0, 96, 0, 96, 0, PCH, 0, 1, 8, 1.0f, 0);
        reduce_kernel<<<(BM_ * D_ + 255) / 256, 256>>>(part, qb + (long)l * D_, nullptr, q2_h,
                                                       BM_ * D_, 8, PCH, D_, 0);

        // qt_h = q2_h @ kw_h^T  (tensor fp16; batched (b,h), K=64)
        hgemm(q2_h, kw_h + (long)l * WL, nullptr, qt_h, nullptr,
              M_, D_, HD_, D_, HD_, D_,
              (long)M_ * D_, HD_, 0, WHD, HMD, (long)M_ * D_,
              0, B_, H_, 1.0f, 0);

        // S-logits written fp16 straight into P  (batched b)
        hgemm(qt_h, lat_h, nullptr, P, nullptr,
              H_ * M_, N_, D_, D_, D_, N_,
              HMD, 0, LAT_B, 0, HMN, 0,
              0, B_, 1, ATTN_SCALE, 0);

        softmax4096h_kernel<<<B_ * H_ * M_, 256>>>(P);

        // ot (fp16) = P @ latent  (batched b; B = latT_h)
        hgemm(P, latT_h, nullptr, ot_h, nullptr,
              H_ * M_, D_, N_, N_, N_, D_,
              HMN, 0, LAT_B, 0, HMD, 0,
              0, B_, 1, 1.0f, 0);

        // o2_h = ot_h @ Wf_h[l] + bias2[l]  (fp16 in, fp32 FFMA; batched (b,h))
        {
            dim3 grid(1, 1, B_ * H_);
            sgemm64h_kernel<<<grid, 128>>>(ot_h, Wf_h + (long)l * WL, o2_h,
                                           bi2 + (long)l * H_ * HD_,
                                           D_, D_, HD_, D_,
                                           HMD, WHD, 0, WHD, (long)M_ * D_, HD_,
                                           HD_, H_);
        }

        // o3 partials = o2 @ ow[l]  (fp16, split-K 8)
        hgemm(o2_h, owT_h + (long)l * D_ * D_, part, nullptr, nullptr,
              BM_, D_, 96, D_, D_, D_,
              0, 96, 0, 96, 0, PCH, 0, 1, 8, 1.0f, 0);
        // x1 = LN(sum(part) + ob + x + qc[l])   (queries reconstructed inline)
        add_ln_red_kernel<<<BM_, 256>>>(part, 8, PCH, ob + (long)l * D_, x,
                                        qc + (long)l * M_ * D_,
                                        g1 + (long)l * D_, be1 + (long)l * D_, x1, x1_h,
                                        nullptr, nullptr);

        // hid = gelu(x1 @ w1 + b1)  (fp16, unsplit, bias+gelu in epilogue)
        hgemm(x1_h, w1T_h + (long)l * D_ * DH_, nullptr, hid_h, b1 + (long)l * DH_,
              BM_, DH_, D_, D_, D_, DH_,
              0, 0, 0, 0, 0, 0, 0, 1, 1, 1.0f, 1);

        // mout partials = hid @ w2  (fp16, split-K 8)
        hgemm(hid_h, w2T_h + (long)l * DH_ * D_, part, nullptr, nullptr,
              BM_, D_, 384, DH_, DH_, D_,
              0, 384, 0, 384, 0, PCH, 0, 1, 8, 1.0f, 0);
        // x = LN(sum(part) + b2 + x1); fuse next layer's queries when l < L-1
        if (l == L_ - 1) {
            add_ln_red_kernel<<<BM_, 256>>>(part, 8, PCH, b2 + (long)l * D_, x1, nullptr,
                                            g2 + (long)l * D_, be2 + (long)l * D_,
                                            out, nullptr, nullptr, nullptr);
        } else {
            add_ln_red_kernel<<<BM_, 256>>>(part, 8, PCH, b2 + (long)l * D_, x1, nullptr,
                                            g2 + (long)l * D_, be2 + (long)l * D_,
                                            x, nullptr,
                                            qc + (long)(l + 1) * M_ * D_, qu_h);
        }
    }
}